// round 11
// baseline (speedup 1.0000x reference)
#include <cuda_runtime.h>

// Problem constants (fixed by reference)
#define CN 64
#define HN 256
#define WN 256
#define L0N 1024   // g0 length (y samples), output innermost dim (j)
#define L1N 1024   // g1 length (x samples), output middle dim (i)
#define AC (-0.75f)

#define JT 128     // j-tile width per block (one float4 per lane)
#define NB 256     // x0 bins
#define SROW 128   // floats per smem row; float4-granularity XOR swizzle

// Precomputed y tap indices / weights
__device__ int4   g_yidx[L0N];
__device__ float4 g_ywt [L0N];
// x samples sorted by x0 bin: packed meta (i | bin<<16) and weights
__device__ int    g_meta[L1N];
__device__ float4 g_swx [L1N];

__device__ __forceinline__ void cubic_w(float t, float* w) {
    // Matches reference _cubic_weights exactly (A = -0.75)
    float t2 = t * t;
    float t3 = t2 * t;
    w[0] = AC * (t3 - 2.0f * t2 + t);
    w[1] = (AC + 2.0f) * t3 - (AC + 3.0f) * t2 + 1.0f;
    float s  = 1.0f - t;
    float s2 = s * s;
    w[2] = (AC + 2.0f) * s2 * s - (AC + 3.0f) * s2 + 1.0f;
    float u = 1.0f + s;
    w[3] = AC * (u * u * u) - 5.0f * AC * (u * u) + 8.0f * AC * u - 4.0f * AC;
}

// Single-block prep: y tables + counting sort of x samples by x0 (parallel scan).
__global__ void prep_kernel(const float* __restrict__ g0,
                            const float* __restrict__ g1) {
    __shared__ int sh_hist[NB];
    __shared__ int sh_scan[NB];
    __shared__ int sh_base[NB];
    const int tid = threadIdx.x;   // 0..1023

    // --- y taps ---
    {
        float x  = (g0[tid] + 1.0f) * 0.5f * (float)(HN - 1);
        float x0 = floorf(x);
        float t  = x - x0;
        int  i0  = (int)x0;
        float w[4];
        cubic_w(t, w);
        int idx[4];
#pragma unroll
        for (int b = 0; b < 4; b++) idx[b] = min(max(i0 - 1 + b, 0), HN - 1);
        g_yidx[tid] = make_int4(idx[0], idx[1], idx[2], idx[3]);
        g_ywt [tid] = make_float4(w[0], w[1], w[2], w[3]);
    }

    // --- x taps: bin by x0, counting sort ---
    float x  = (g1[tid] + 1.0f) * 0.5f * (float)(WN - 1);
    float x0 = floorf(x);
    float t  = x - x0;
    int bin  = min(max((int)x0, 0), NB - 1);
    float w[4];
    cubic_w(t, w);

    if (tid < NB) sh_hist[tid] = 0;
    __syncthreads();
    int rank = atomicAdd(&sh_hist[bin], 1);
    __syncthreads();

    // Parallel inclusive scan (Hillis-Steele) over 256 bins
    if (tid < NB) sh_scan[tid] = sh_hist[tid];
    __syncthreads();
#pragma unroll
    for (int off = 1; off < NB; off <<= 1) {
        int v = 0;
        if (tid < NB && tid >= off) v = sh_scan[tid - off];
        __syncthreads();
        if (tid < NB) sh_scan[tid] += v;
        __syncthreads();
    }
    if (tid < NB) sh_base[tid] = sh_scan[tid] - sh_hist[tid];  // exclusive
    __syncthreads();

    int pos = sh_base[bin] + rank;
    g_swx [pos] = make_float4(w[0], w[1], w[2], w[3]);
    g_meta[pos] = tid | (bin << 16);
}

// Fused kernel: one block = (c, 128-wide j tile), 1024 threads, 128 KB smem.
// Phase A: warp w owns f-group f=w (4 consecutive j). Per x: 16 independent
//          coalesced LDG.32 (MLP=16) -> one conflict-free swizzled STS.128.
// Phase B: PERFECTLY BALANCED — warp w processes sorted entries
//          [w*32, w*32+32): per entry 4 conflict-free LDS.128 tap rows,
//          16 FFMA, 1 STG.128. No bins, no divergence, no imbalance.
__global__ void __launch_bounds__(1024, 1)
fused_kernel(const float* __restrict__ v, float* __restrict__ out) {
    extern __shared__ float sY[];          // [256][128] swizzled

    const int tid  = threadIdx.x;
    const int lane = tid & 31;
    const int wid  = tid >> 5;             // 0..31
    const int jt = blockIdx.x * JT;        // j tile base
    const int c  = blockIdx.y;

    const float* vc = v + (size_t)c * (HN * WN);

    // ---- Phase A: y-interpolation into swizzled smem ----
    {
        const int f  = wid;                // f-group 0..31
        const int jl = f << 2;
        const int4   yi0 = g_yidx[jt + jl + 0];
        const int4   yi1 = g_yidx[jt + jl + 1];
        const int4   yi2 = g_yidx[jt + jl + 2];
        const int4   yi3 = g_yidx[jt + jl + 3];
        const float4 wy0 = g_ywt [jt + jl + 0];
        const float4 wy1 = g_ywt [jt + jl + 1];
        const float4 wy2 = g_ywt [jt + jl + 2];
        const float4 wy3 = g_ywt [jt + jl + 3];
#pragma unroll
        for (int xc = 0; xc < 8; xc++) {
            const int x = xc * 32 + lane;
            const float* px = vc + x;
            float4 st;
            st.x = wy0.x * __ldg(px + yi0.x * WN) + wy0.y * __ldg(px + yi0.y * WN)
                 + wy0.z * __ldg(px + yi0.z * WN) + wy0.w * __ldg(px + yi0.w * WN);
            st.y = wy1.x * __ldg(px + yi1.x * WN) + wy1.y * __ldg(px + yi1.y * WN)
                 + wy1.z * __ldg(px + yi1.z * WN) + wy1.w * __ldg(px + yi1.w * WN);
            st.z = wy2.x * __ldg(px + yi2.x * WN) + wy2.y * __ldg(px + yi2.y * WN)
                 + wy2.z * __ldg(px + yi2.z * WN) + wy2.w * __ldg(px + yi2.w * WN);
            st.w = wy3.x * __ldg(px + yi3.x * WN) + wy3.y * __ldg(px + yi3.y * WN)
                 + wy3.z * __ldg(px + yi3.z * WN) + wy3.w * __ldg(px + yi3.w * WN);
            *(float4*)(sY + x * SROW + ((f ^ (x & 31)) << 2)) = st;
        }
    }
    __syncthreads();

    // ---- Phase B: balanced sorted-entry sweep ----
    float* outc = out + ((size_t)c * L1N) * L0N + jt + (lane << 2);

    // swizzled row load: row x, logical float4 index = lane
    #define LOADROW(x) (*(const float4*)(sY + (x) * SROW + ((lane ^ ((x) & 31)) << 2)))

    const int kbase = wid * 32;            // 32 entries per warp

#pragma unroll 2
    for (int t = 0; t < 32; t++) {
        const int    meta = g_meta[kbase + t];
        const float4 wx   = g_swx [kbase + t];
        const int i = meta & 0xFFFF;
        const int b = meta >> 16;

        const float4 a0 = LOADROW(max(b - 1, 0));
        const float4 a1 = LOADROW(b);
        const float4 a2 = LOADROW(min(b + 1, WN - 1));
        const float4 a3 = LOADROW(min(b + 2, WN - 1));

        float4 acc;
        acc.x = wx.x * a0.x + wx.y * a1.x + wx.z * a2.x + wx.w * a3.x;
        acc.y = wx.x * a0.y + wx.y * a1.y + wx.z * a2.y + wx.w * a3.y;
        acc.z = wx.x * a0.z + wx.y * a1.z + wx.z * a2.z + wx.w * a3.z;
        acc.w = wx.x * a0.w + wx.y * a1.w + wx.z * a2.w + wx.w * a3.w;

        *(float4*)(outc + (size_t)i * L0N) = acc;
    }
    #undef LOADROW
}

extern "C" void kernel_launch(void* const* d_in, const int* in_sizes, int n_in,
                              void* d_out, int out_size) {
    const float* values = (const float*)d_in[0];   // (1,64,256,256)
    const float* g0     = (const float*)d_in[1];   // (1024,)
    const float* g1     = (const float*)d_in[2];   // (1024,)
    float* out = (float*)d_out;                    // (1,64,1024,1024)

    static int smem_set = 0;
    const int smem_bytes = HN * SROW * sizeof(float);  // 256*128*4 = 131072
    if (!smem_set) {
        cudaFuncSetAttribute(fused_kernel,
                             cudaFuncAttributeMaxDynamicSharedMemorySize,
                             smem_bytes);
        smem_set = 1;
    }

    prep_kernel<<<1, 1024>>>(g0, g1);

    dim3 grid(L0N / JT, CN);               // (8, 64) = 512 blocks
    fused_kernel<<<grid, 1024, smem_bytes>>>(values, out);
}